// round 1
// baseline (speedup 1.0000x reference)
#include <cuda_runtime.h>
#include <math.h>

#define SEQ 2048
#define BATCH 2
#define ROWS (BATCH*SEQ)   // 4096
#define NHEADS 16
#define QHD 192
#define NOPE 128
#define ROPE_D 64
#define VHD 128

// ---------------- scratch (device globals; no allocation allowed) ----------------
__device__ float g_qlora[(size_t)ROWS*1536];
__device__ float g_q[(size_t)ROWS*3072];
__device__ float g_ckv[(size_t)ROWS*576];
__device__ float g_cnorm[(size_t)ROWS*512];
__device__ float g_kv[(size_t)ROWS*4096];
__device__ float g_kpe[(size_t)ROWS*64];
__device__ float g_attn[(size_t)ROWS*2048];

// ---------------- generic SGEMM: C[M,N] = A[M,K] @ B[N,K]^T ----------------
// 64x64 block tile, BK=16, 256 threads, 4x4 per-thread register tile.
__global__ __launch_bounds__(256) void sgemm_tn(const float* __restrict__ A,
                                                const float* __restrict__ B,
                                                float* __restrict__ C,
                                                int M, int N, int K) {
    __shared__ float As[16][68];
    __shared__ float Bs[16][68];
    const int tid = threadIdx.x;
    const int tx = tid & 15, ty = tid >> 4;
    const int m0 = blockIdx.y * 64, n0 = blockIdx.x * 64;
    const float* Ap = A + (size_t)m0 * K;
    const float* Bp = B + (size_t)n0 * K;
    float acc[4][4] = {};
    for (int k0 = 0; k0 < K; k0 += 16) {
        #pragma unroll
        for (int u = 0; u < 4; u++) {
            int idx = tid + u * 256;
            int r = idx >> 4, c = idx & 15;
            As[c][r] = Ap[(size_t)r * K + k0 + c];
            Bs[c][r] = Bp[(size_t)r * K + k0 + c];
        }
        __syncthreads();
        #pragma unroll
        for (int kk = 0; kk < 16; kk++) {
            float4 a4 = *(const float4*)(&As[kk][ty * 4]);
            float4 b4 = *(const float4*)(&Bs[kk][tx * 4]);
            float av[4] = {a4.x, a4.y, a4.z, a4.w};
            float bv[4] = {b4.x, b4.y, b4.z, b4.w};
            #pragma unroll
            for (int i = 0; i < 4; i++)
                #pragma unroll
                for (int j = 0; j < 4; j++)
                    acc[i][j] += av[i] * bv[j];
        }
        __syncthreads();
    }
    #pragma unroll
    for (int i = 0; i < 4; i++)
        #pragma unroll
        for (int j = 0; j < 4; j++)
            C[(size_t)(m0 + ty * 4 + i) * N + n0 + tx * 4 + j] = acc[i][j];
}

// ---------------- RMSNorm: one block per row ----------------
__global__ __launch_bounds__(256) void rmsnorm_k(const float* __restrict__ X,
                                                 const float* __restrict__ w,
                                                 float* __restrict__ Y,
                                                 int W, int ldx, int ldy) {
    int row = blockIdx.x;
    const float* x = X + (size_t)row * ldx;
    float ss = 0.f;
    for (int i = threadIdx.x; i < W; i += 256) { float v = x[i]; ss += v * v; }
    __shared__ float red[256];
    red[threadIdx.x] = ss;
    __syncthreads();
    for (int s = 128; s > 0; s >>= 1) {
        if (threadIdx.x < s) red[threadIdx.x] += red[threadIdx.x + s];
        __syncthreads();
    }
    float inv = rsqrtf(red[0] / (float)W + 1e-6f);
    float* y = Y + (size_t)row * ldy;
    for (int i = threadIdx.x; i < W; i += 256) y[i] = w[i] * (x[i] * inv);
}

// ---------------- YaRN RoPE ----------------
// One block per (b,s) row. Warps 0..15: q_pe head h in-place; warp 16: k_pe -> g_kpe.
// Interleaved-to-half: out[j]    = x[2j]*cos - x[2j+1]*sin
//                      out[32+j] = x[2j+1]*cos + x[2j]*sin
__global__ __launch_bounds__(544) void rope_k(const int* __restrict__ pos_ids) {
    int row = blockIdx.x;
    int t = threadIdx.x;
    int h = t >> 5, j = t & 31;
    float pos = (float)pos_ids[row];
    float fe = powf(10000.0f, -(float)j / 32.0f);       // freq_extra
    float ramp = fminf(fmaxf(((float)j - 10.0f) / 13.0f, 0.f), 1.f);
    float invf = (fe / 40.0f) * ramp + fe * (1.0f - ramp);
    float ang = pos * invf;
    float s, c;
    sincosf(ang, &s, &c);
    if (h < NHEADS) {
        float* base = g_q + (size_t)row * 3072 + h * QHD + NOPE;
        float x0 = base[2 * j], x1 = base[2 * j + 1];
        __syncwarp();
        base[j]      = x0 * c - x1 * s;
        base[32 + j] = x1 * c + x0 * s;
    } else {
        const float* src = g_ckv + (size_t)row * 576 + 512;
        float x0 = src[2 * j], x1 = src[2 * j + 1];
        float* dst = g_kpe + (size_t)row * 64;
        dst[j]      = x0 * c - x1 * s;
        dst[32 + j] = x1 * c + x0 * s;
    }
}

// ---------------- Flash attention (causal, online softmax) ----------------
// Grid (SEQ/64, 16 heads, batch). 256 threads. 64 q-rows x 64 k-cols per tile.
#define QP 193   // pitch for Qs/Ks (192 + 1, odd%8 -> 2-way max conflicts)
#define VP 132   // pitch for Vs (128 + 4, 16B-aligned rows)
#define PP 68    // pitch for Ps
#define FLASH_SMEM ((64*QP*2 + 64*VP + 64*PP) * 4)

__global__ __launch_bounds__(256) void flash_k(float scale) {
    extern __shared__ float sm[];
    float* Qs = sm;                    // [64][QP]
    float* Ks = Qs + 64 * QP;          // [64][QP]
    float* Vs = Ks + 64 * QP;          // [64][VP]
    float* Ps = Vs + 64 * VP;          // [64][PP]
    const int qb = blockIdx.x, h = blockIdx.y, b = blockIdx.z;
    const int tid = threadIdx.x;
    const int tx = tid & 15, ty = tid >> 4;
    const size_t bs0 = (size_t)b * SEQ;

    for (int idx = tid; idx < 64 * 192; idx += 256) {
        int r = idx / 192, c = idx - r * 192;
        Qs[r * QP + c] = g_q[(bs0 + qb * 64 + r) * 3072 + h * QHD + c];
    }
    float m_i[4], l_i[4], o[4][8];
    #pragma unroll
    for (int i = 0; i < 4; i++) {
        m_i[i] = -1e30f; l_i[i] = 0.f;
        #pragma unroll
        for (int j = 0; j < 8; j++) o[i][j] = 0.f;
    }
    __syncthreads();

    for (int kb = 0; kb <= qb; kb++) {
        for (int idx = tid; idx < 64 * 192; idx += 256) {
            int r = idx / 192, c = idx - r * 192;
            int sk = kb * 64 + r;
            float v;
            if (c < NOPE) v = g_kv[(bs0 + sk) * 4096 + h * 256 + c];
            else          v = g_kpe[(bs0 + sk) * 64 + (c - NOPE)];
            Ks[r * QP + c] = v;
        }
        for (int idx = tid; idx < 64 * 128; idx += 256) {
            int r = idx >> 7, c = idx & 127;
            Vs[r * VP + c] = g_kv[(bs0 + kb * 64 + r) * 4096 + h * 256 + NOPE + c];
        }
        __syncthreads();

        float acc[4][4] = {};
        for (int kk = 0; kk < 192; kk++) {
            float av[4], bv[4];
            #pragma unroll
            for (int i = 0; i < 4; i++) av[i] = Qs[(ty * 4 + i) * QP + kk];
            #pragma unroll
            for (int j = 0; j < 4; j++) bv[j] = Ks[(tx * 4 + j) * QP + kk];
            #pragma unroll
            for (int i = 0; i < 4; i++)
                #pragma unroll
                for (int j = 0; j < 4; j++)
                    acc[i][j] += av[i] * bv[j];
        }

        bool diag = (kb == qb);
        #pragma unroll
        for (int i = 0; i < 4; i++) {
            int qi = qb * 64 + ty * 4 + i;
            float rm = -1e30f;
            #pragma unroll
            for (int j = 0; j < 4; j++) {
                float sv = acc[i][j] * scale;
                if (diag && (kb * 64 + tx * 4 + j > qi)) sv = -1e30f;
                acc[i][j] = sv;
                rm = fmaxf(rm, sv);
            }
            #pragma unroll
            for (int off = 8; off > 0; off >>= 1)
                rm = fmaxf(rm, __shfl_xor_sync(0xffffffffu, rm, off));
            float mnew = fmaxf(m_i[i], rm);
            float alpha = __expf(m_i[i] - mnew);
            float rs = 0.f;
            #pragma unroll
            for (int j = 0; j < 4; j++) {
                float p = __expf(acc[i][j] - mnew);
                Ps[(ty * 4 + i) * PP + tx * 4 + j] = p;
                rs += p;
            }
            #pragma unroll
            for (int off = 8; off > 0; off >>= 1)
                rs += __shfl_xor_sync(0xffffffffu, rs, off);
            l_i[i] = l_i[i] * alpha + rs;
            m_i[i] = mnew;
            #pragma unroll
            for (int j = 0; j < 8; j++) o[i][j] *= alpha;
        }
        __syncthreads();

        for (int kk = 0; kk < 64; kk++) {
            float pv[4];
            #pragma unroll
            for (int i = 0; i < 4; i++) pv[i] = Ps[(ty * 4 + i) * PP + kk];
            float4 v0 = *(const float4*)&Vs[kk * VP + tx * 8];
            float4 v1 = *(const float4*)&Vs[kk * VP + tx * 8 + 4];
            float vv[8] = {v0.x, v0.y, v0.z, v0.w, v1.x, v1.y, v1.z, v1.w};
            #pragma unroll
            for (int i = 0; i < 4; i++)
                #pragma unroll
                for (int j = 0; j < 8; j++)
                    o[i][j] += pv[i] * vv[j];
        }
        __syncthreads();
    }

    #pragma unroll
    for (int i = 0; i < 4; i++) {
        float invl = 1.0f / l_i[i];
        #pragma unroll
        for (int j = 0; j < 8; j++)
            g_attn[(bs0 + qb * 64 + ty * 4 + i) * 2048 + h * VHD + tx * 8 + j] =
                o[i][j] * invl;
    }
}

// ---------------- launch ----------------
extern "C" void kernel_launch(void* const* d_in, const int* in_sizes, int n_in,
                              void* d_out, int out_size) {
    const float* hs      = (const float*)d_in[0];
    const int*   pos     = (const int*)  d_in[1];
    const float* wq_a    = (const float*)d_in[2];
    const float* q_a_ln  = (const float*)d_in[3];
    const float* wq_b    = (const float*)d_in[4];
    const float* wkv_a   = (const float*)d_in[5];
    const float* kv_a_ln = (const float*)d_in[6];
    const float* wkv_b   = (const float*)d_in[7];
    const float* wo      = (const float*)d_in[8];
    float* out = (float*)d_out;

    float *qlora, *q, *ckv, *cnorm, *kv, *kpe, *attn;
    cudaGetSymbolAddress((void**)&qlora, g_qlora);
    cudaGetSymbolAddress((void**)&q,     g_q);
    cudaGetSymbolAddress((void**)&ckv,   g_ckv);
    cudaGetSymbolAddress((void**)&cnorm, g_cnorm);
    cudaGetSymbolAddress((void**)&kv,    g_kv);
    cudaGetSymbolAddress((void**)&kpe,   g_kpe);
    cudaGetSymbolAddress((void**)&attn,  g_attn);

    // softmax scale: 192^-0.5 * m^2, m = 0.1*ln(40) + 1
    double m = 0.1 * log(40.0) + 1.0;
    float scale = (float)((1.0 / sqrt(192.0)) * m * m);

    cudaFuncSetAttribute(flash_k, cudaFuncAttributeMaxDynamicSharedMemorySize,
                         FLASH_SMEM);

    dim3 blk(256);
    // q_lora = hs @ wq_a^T
    sgemm_tn<<<dim3(1536 / 64, ROWS / 64), blk>>>(hs, wq_a, qlora, ROWS, 1536, 2048);
    // rmsnorm in-place over 1536
    rmsnorm_k<<<ROWS, 256>>>(qlora, q_a_ln, qlora, 1536, 1536, 1536);
    // q = qlora_n @ wq_b^T
    sgemm_tn<<<dim3(3072 / 64, ROWS / 64), blk>>>(qlora, wq_b, q, ROWS, 3072, 1536);
    // ckv = hs @ wkv_a^T
    sgemm_tn<<<dim3(576 / 64, ROWS / 64), blk>>>(hs, wkv_a, ckv, ROWS, 576, 2048);
    // rmsnorm(compressed[...,:512]) -> cnorm
    rmsnorm_k<<<ROWS, 256>>>(ckv, kv_a_ln, cnorm, 512, 576, 512);
    // kv = cnorm @ wkv_b^T
    sgemm_tn<<<dim3(4096 / 64, ROWS / 64), blk>>>(cnorm, wkv_b, kv, ROWS, 4096, 512);
    // rope: q_pe in place, k_pe -> g_kpe
    rope_k<<<ROWS, 544>>>(pos);
    // causal flash attention -> g_attn [rows, heads*128]
    flash_k<<<dim3(SEQ / 64, NHEADS, BATCH), 256, FLASH_SMEM>>>(scale);
    // out = attn @ wo^T
    sgemm_tn<<<dim3(2048 / 64, ROWS / 64), blk>>>(attn, wo, out, ROWS, 2048, 2048);
}